// round 12
// baseline (speedup 1.0000x reference)
#include <cuda_runtime.h>
#include <cstdint>

// Problem constants
#define N_ 64
#define L_ 512
#define T_ 128
#define D_ 1024
#define D4 (D_ / 4)          // 256 float4 per row
#define WARPS_A 8
#define ROWS_PER_WARP 8
#define TILE_ROWS (WARPS_A * ROWS_PER_WARP)   // 64
#define NTILES (L_ / TILE_ROWS)               // 8

// Scratch (allocation-free device globals)
__device__ float g_e[N_][L_];                 // unnormalized exp(scores)
__device__ float g_part[NTILES][N_][D_];      // per-tile weighted sums, 2 MB
__device__ float g_zpart[NTILES][N_];         // per-tile sum of exps
__device__ float g_gn[N_][D_];                // normalized weighted sums
__device__ float g_pn[N_][L_];                // normalized probs

// ---------------------------------------------------------------------------
// Pass 1: ONE DRAM read of f1. Warp owns 8 rows.
//   Phase 1: streaming dots (no retention, no barrier, deep MLP) -> e[8].
//   Phase 2: re-read own 8 rows (32 KB, L2-hot) and FMA into acc[8].
// launch_bounds(256,3) caps regs at ~84 -> 3 CTAs/SM, 24 warps.
// Grid (NTILES=8, N=64) = 512 CTAs x 256 threads.
// ---------------------------------------------------------------------------
__global__ void __launch_bounds__(256, 3) pass1_kernel(
    const float* __restrict__ f1, const float* __restrict__ w)
{
    __shared__ float4 wsh[D4];                 // 4 KB
    __shared__ float4 accsh[WARPS_A][D4];      // 32 KB
    __shared__ float  zsh[WARPS_A];

    int tid = threadIdx.x, lane = tid & 31, warp = tid >> 5;
    if (tid < D4) wsh[tid] = reinterpret_cast<const float4*>(w)[tid];
    __syncthreads();

    int tile = blockIdx.x, n = blockIdx.y;
    int row0 = tile * TILE_ROWS + warp * ROWS_PER_WARP;
    const float4* base = reinterpret_cast<const float4*>(f1)
                         + ((size_t)n * L_ + row0) * D4;

    // ---- Phase 1: dots for 8 rows, streaming
    float e[ROWS_PER_WARP];
    float zacc = 0.f;
#pragma unroll 2
    for (int r = 0; r < ROWS_PER_WARP; ++r) {
        const float4* p = base + (size_t)r * D4;
        float d0 = 0.f, d1 = 0.f;
#pragma unroll
        for (int j = 0; j < 8; j += 2) {
            float4 xa = p[lane + 32 * j];
            float4 xb = p[lane + 32 * (j + 1)];
            float4 wa = wsh[lane + 32 * j];
            float4 wb = wsh[lane + 32 * (j + 1)];
            d0 += xa.x * wa.x + xa.y * wa.y + xa.z * wa.z + xa.w * wa.w;
            d1 += xb.x * wb.x + xb.y * wb.y + xb.z * wb.z + xb.w * wb.w;
        }
        float d = d0 + d1;
#pragma unroll
        for (int o = 16; o > 0; o >>= 1)
            d += __shfl_xor_sync(0xffffffffu, d, o);
        e[r] = __expf(d);          // scores are O(1): no overflow, no max-shift
        zacc += e[r];
    }
    if (lane == 0) {
#pragma unroll
        for (int r = 0; r < ROWS_PER_WARP; ++r)
            g_e[n][row0 + r] = e[r];
    }

    // ---- Phase 2: re-read rows (L2-hot) and accumulate e-weighted sum
    float4 acc[8];
#pragma unroll
    for (int j = 0; j < 8; ++j) acc[j] = make_float4(0.f, 0.f, 0.f, 0.f);

#pragma unroll 1
    for (int r = 0; r < ROWS_PER_WARP; ++r) {
        const float4* p = base + (size_t)r * D4;
        float er = e[r];
#pragma unroll
        for (int j = 0; j < 8; ++j) {
            float4 x = p[lane + 32 * j];
            acc[j].x = fmaf(er, x.x, acc[j].x);
            acc[j].y = fmaf(er, x.y, acc[j].y);
            acc[j].z = fmaf(er, x.z, acc[j].z);
            acc[j].w = fmaf(er, x.w, acc[j].w);
        }
    }

#pragma unroll
    for (int j = 0; j < 8; ++j) accsh[warp][lane + 32 * j] = acc[j];
    if (lane == 0) zsh[warp] = zacc;
    __syncthreads();

    // cross-warp reduce: 256 threads over D4=256 float4 columns
    float4 t = accsh[0][tid];
#pragma unroll
    for (int k = 1; k < WARPS_A; ++k) {
        float4 a = accsh[k][tid];
        t.x += a.x; t.y += a.y; t.z += a.z; t.w += a.w;
    }
    reinterpret_cast<float4*>(&g_part[tile][n][0])[tid] = t;
    if (tid == 0) {
        float z = 0.f;
#pragma unroll
        for (int k = 0; k < WARPS_A; ++k) z += zsh[k];
        g_zpart[tile][n] = z;
    }
}

// ---------------------------------------------------------------------------
// Pass 2a (tiny, done ONCE): combine tile partials, normalize.
// Grid (N=64, 2) x 256 threads: threads 0-127 combine g columns for one half
// of D; threads 128-255 normalize probs for one half of L.
// ---------------------------------------------------------------------------
__global__ void __launch_bounds__(256) pass2a_kernel()
{
    int n = blockIdx.x, half = blockIdx.y;
    int tid = threadIdx.x;

    float z = 0.f;
#pragma unroll
    for (int k = 0; k < NTILES; ++k) z += g_zpart[k][n];
    float inv = __frcp_rn(z);

    if (tid < 128) {
        int col = half * 128 + tid;
        float4 g = reinterpret_cast<const float4*>(&g_part[0][n][0])[col];
#pragma unroll
        for (int k = 1; k < NTILES; ++k) {
            float4 a = reinterpret_cast<const float4*>(&g_part[k][n][0])[col];
            g.x += a.x; g.y += a.y; g.z += a.z; g.w += a.w;
        }
        g.x *= inv; g.y *= inv; g.z *= inv; g.w *= inv;
        reinterpret_cast<float4*>(&g_gn[n][0])[col] = g;
    } else {
        int l = half * 256 + (tid - 128) * 2;
        g_pn[n][l]     = g_e[n][l]     * inv;
        g_pn[n][l + 1] = g_e[n][l + 1] * inv;
    }
}

// ---------------------------------------------------------------------------
// Pass 2b: pure broadcast (no combine). Grid (N=64, 4) x 512 threads;
// CTA c covers T-rows [c*32, c*32+32). Reads 6 KB, streams 192 KB of
// evict-first stores.
// ---------------------------------------------------------------------------
__global__ void __launch_bounds__(512) pass2b_kernel(
    float* __restrict__ fhat, float* __restrict__ att)
{
    __shared__ float4 gsh[D4];                    // 4 KB normalized sums
    __shared__ __align__(16) float esh[L_];       // 2 KB normalized probs

    int n = blockIdx.x, c = blockIdx.y;
    int tid = threadIdx.x;

    if (tid < D4) gsh[tid] = reinterpret_cast<const float4*>(&g_gn[n][0])[tid];
    esh[tid] = g_pn[n][tid];
    __syncthreads();

    // att[n, c*32 + r, :] for r in [0,32): 32 rows x 128 float4 = 4096 f4
    {
        const float4* es4 = reinterpret_cast<const float4*>(esh);
        float* arow = att + (size_t)n * T_ * L_ + (size_t)c * 32 * L_;
#pragma unroll
        for (int k = tid; k < 32 * (L_ / 4); k += 512) {
            int r = k >> 7, f = k & 127;
            __stcs(reinterpret_cast<float4*>(arow + (size_t)r * L_) + f, es4[f]);
        }
    }

    // fhat[n, c*32 + r, :] for r in [0,32): 32 rows x 256 float4 = 8192 f4
    {
        float4* orow = reinterpret_cast<float4*>(fhat)
                       + ((size_t)n * T_ + (size_t)c * 32) * D4;
#pragma unroll
        for (int k = tid; k < 32 * D4; k += 512) {
            int r = k >> 8, f = k & 255;
            __stcs(orow + (size_t)r * D4 + f, gsh[f]);
        }
    }
}

// ---------------------------------------------------------------------------
extern "C" void kernel_launch(void* const* d_in, const int* in_sizes, int n_in,
                              void* d_out, int out_size)
{
    const float* f1 = (const float*)d_in[0];  // [N,L,D]
    // d_in[1] = feature_2 : unused (softmax shift-invariance cancels it)
    const float* w  = (const float*)d_in[2];  // [D]
    // d_in[3] = b : unused (cancels in softmax)

    float* fhat = (float*)d_out;                         // [N,T,D]
    float* att  = (float*)d_out + (size_t)N_ * T_ * D_;  // [N,T,L]

    pass1_kernel <<< dim3(NTILES, N_), 256 >>> (f1, w);
    pass2a_kernel<<< dim3(N_, 2), 256 >>> ();
    pass2b_kernel<<< dim3(N_, 4), 512 >>> (fhat, att);
}

// round 13
// speedup vs baseline: 1.5270x; 1.5270x over previous
#include <cuda_runtime.h>
#include <cstdint>

// Problem constants
#define N_ 64
#define L_ 512
#define T_ 128
#define D_ 1024
#define D4 (D_ / 4)          // 256 float4 per row
#define NPAIRS 4             // warp-pairs per CTA (8 warps, 256 threads)
#define ROWS_PER_PAIR 8
#define TILE_ROWS (NPAIRS * ROWS_PER_PAIR)    // 32
#define NTILES (L_ / TILE_ROWS)               // 16

// Scratch (allocation-free device globals)
__device__ float g_e[N_][L_];   // unnormalized exp(scores)
__device__ float g_g[N_][D_];   // atomically accumulated weighted sums
__device__ float g_z[N_];       // atomically accumulated sum of exps

// ---------------------------------------------------------------------------
// Kernel 0: zero the atomic accumulators (device globals persist across
// graph replays). Kernel boundary orders this before pass1's atomics.
// ---------------------------------------------------------------------------
__global__ void zero_kernel()
{
    int n = blockIdx.x, tid = threadIdx.x;
    reinterpret_cast<float4*>(&g_g[n][0])[tid] = make_float4(0.f, 0.f, 0.f, 0.f);
    if (tid == 0) g_z[n] = 0.f;
}

// ---------------------------------------------------------------------------
// Pass 1: ONE DRAM read of f1 (proven 29.5us shape). Two-warp teams: each
// warp holds a HALF row (x[4], acc[4] ~ 58 regs). Partial dots exchanged via
// double-buffered smem + 1 barrier per row. e = exp(dot): no max-shift needed
// (scores are O(1)); exp-weighted partials are associative -> REDG combine.
// Grid (NTILES=16, N=64) = 1024 CTAs x 256 threads.
// ---------------------------------------------------------------------------
__global__ void __launch_bounds__(256) pass1_kernel(
    const float* __restrict__ f1, const float* __restrict__ w)
{
    __shared__ float4 wsh[D4];                   // 4 KB
    __shared__ float4 accsh[NPAIRS][D4];         // 16 KB
    __shared__ float  sdot[2][8];                // double-buffered partial dots
    __shared__ float  zsh[NPAIRS];

    int tid = threadIdx.x, lane = tid & 31, warp = tid >> 5;
    int pair = warp >> 1, h = warp & 1;          // h: which half of the row
    wsh[tid] = reinterpret_cast<const float4*>(w)[tid];
    __syncthreads();

    int tile = blockIdx.x, n = blockIdx.y;
    int row0 = tile * TILE_ROWS + pair * ROWS_PER_PAIR;
    const float4* base = reinterpret_cast<const float4*>(f1)
                         + ((size_t)n * L_ + row0) * D4 + h * (D4 / 2);

    float4 acc[4];
#pragma unroll
    for (int j = 0; j < 4; ++j) acc[j] = make_float4(0.f, 0.f, 0.f, 0.f);
    float zacc = 0.f;

#pragma unroll 1
    for (int r = 0; r < ROWS_PER_PAIR; ++r) {
        const float4* p = base + (size_t)r * D4;
        float4 x[4];
#pragma unroll
        for (int j = 0; j < 4; ++j) x[j] = p[lane + 32 * j];

        float d = 0.f;
#pragma unroll
        for (int j = 0; j < 4; ++j) {
            float4 ww = wsh[h * (D4 / 2) + lane + 32 * j];
            d += x[j].x * ww.x + x[j].y * ww.y + x[j].z * ww.z + x[j].w * ww.w;
        }
#pragma unroll
        for (int o = 16; o > 0; o >>= 1)
            d += __shfl_xor_sync(0xffffffffu, d, o);
        if (lane == 0) sdot[r & 1][warp] = d;
        __syncthreads();

        float e = __expf(sdot[r & 1][pair * 2] + sdot[r & 1][pair * 2 + 1]);
        if (h == 0) {
            zacc += e;
            if (lane == 0) g_e[n][row0 + r] = e;
        }
#pragma unroll
        for (int j = 0; j < 4; ++j) {
            acc[j].x = fmaf(e, x[j].x, acc[j].x);
            acc[j].y = fmaf(e, x[j].y, acc[j].y);
            acc[j].z = fmaf(e, x[j].z, acc[j].z);
            acc[j].w = fmaf(e, x[j].w, acc[j].w);
        }
    }

#pragma unroll
    for (int j = 0; j < 4; ++j)
        accsh[pair][h * (D4 / 2) + lane + 32 * j] = acc[j];
    if (h == 0 && lane == 0) zsh[pair] = zacc;
    __syncthreads();

    // cross-pair reduce then REDG into global accumulators (no g_part, no
    // combine kernel). 256 threads x 4 floats = 1024 spread-address atomics.
    float4 t = accsh[0][tid];
#pragma unroll
    for (int k = 1; k < NPAIRS; ++k) {
        float4 a = accsh[k][tid];
        t.x += a.x; t.y += a.y; t.z += a.z; t.w += a.w;
    }
    float* gcol = &g_g[n][tid * 4];
    atomicAdd(gcol + 0, t.x);
    atomicAdd(gcol + 1, t.y);
    atomicAdd(gcol + 2, t.z);
    atomicAdd(gcol + 3, t.w);
    if (tid == 0)
        atomicAdd(&g_z[n], (zsh[0] + zsh[1]) + (zsh[2] + zsh[3]));
}

// ---------------------------------------------------------------------------
// Pass 2: pure broadcast, normalize in-kernel. Grid (N=64, 4) x 512 threads;
// CTA c covers T-rows [c*32, c*32+32). Reads ~6 KB (L2-broadcast), streams
// 192 KB of evict-first stores.
// ---------------------------------------------------------------------------
__global__ void __launch_bounds__(512) pass2_kernel(
    float* __restrict__ fhat, float* __restrict__ att)
{
    __shared__ float4 gsh[D4];                    // 4 KB normalized sums
    __shared__ __align__(16) float esh[L_];       // 2 KB normalized probs

    int n = blockIdx.x, c = blockIdx.y;
    int tid = threadIdx.x;

    float inv = __frcp_rn(g_z[n]);
    if (tid < D4) {
        float4 g = reinterpret_cast<const float4*>(&g_g[n][0])[tid];
        g.x *= inv; g.y *= inv; g.z *= inv; g.w *= inv;
        gsh[tid] = g;
    }
    esh[tid] = g_e[n][tid] * inv;
    __syncthreads();

    // att[n, c*32 + r, :] for r in [0,32): 32 rows x 128 float4 = 4096 f4
    {
        const float4* es4 = reinterpret_cast<const float4*>(esh);
        float* arow = att + (size_t)n * T_ * L_ + (size_t)c * 32 * L_;
#pragma unroll
        for (int k = tid; k < 32 * (L_ / 4); k += 512) {
            int r = k >> 7, f = k & 127;
            __stcs(reinterpret_cast<float4*>(arow + (size_t)r * L_) + f, es4[f]);
        }
    }

    // fhat[n, c*32 + r, :] for r in [0,32): 32 rows x 256 float4 = 8192 f4
    {
        float4* orow = reinterpret_cast<float4*>(fhat)
                       + ((size_t)n * T_ + (size_t)c * 32) * D4;
#pragma unroll
        for (int k = tid; k < 32 * D4; k += 512) {
            int r = k >> 8, f = k & 255;
            __stcs(orow + (size_t)r * D4 + f, gsh[f]);
        }
    }
}

// ---------------------------------------------------------------------------
extern "C" void kernel_launch(void* const* d_in, const int* in_sizes, int n_in,
                              void* d_out, int out_size)
{
    const float* f1 = (const float*)d_in[0];  // [N,L,D]
    // d_in[1] = feature_2 : unused (softmax shift-invariance cancels it)
    const float* w  = (const float*)d_in[2];  // [D]
    // d_in[3] = b : unused (cancels in softmax)

    float* fhat = (float*)d_out;                         // [N,T,D]
    float* att  = (float*)d_out + (size_t)N_ * T_ * D_;  // [N,T,L]

    zero_kernel <<< N_, 256 >>> ();
    pass1_kernel<<< dim3(NTILES, N_), 256 >>> (f1, w);
    pass2_kernel<<< dim3(N_, 4), 512 >>> (fhat, att);
}